// round 4
// baseline (speedup 1.0000x reference)
#include <cuda_runtime.h>
#include <cstddef>

// Problem constants (fixed shapes for this problem instance)
#define BB    4096      // batch
#define NXD   64        // state dim
#define NUD   16        // control dim
#define HH    50        // horizon
#define HIDD  256       // hidden dim
#define ZD    80        // NX + NU
#define W1STRIDE 260    // padded smem row stride for W1 (multiple of 4, stride%32==4 -> conflict-free f4)
#define W2STRIDE 260    // padded smem row stride for W2^T

// Output layout (flattened tuple, in reference return order)
#define OFF_U      0
#define OFF_XTRAJ  (BB*NUD)                                   // 65536
#define OFF_XPRED  (OFF_XTRAJ + BB*(HH+1)*NXD)                // 13434880
#define OFF_GX     (OFF_XPRED + BB*HH*NXD)                    // 26542080
#define OFF_GU     (OFF_GX + BB*HH*NXD)                       // 39649280

// Scratch: u9 = controls used in the last rollout (before the final noise update)
__device__ float g_u9[BB * HH * NUD];

// ---------------------------------------------------------------------------
// Prep: u9[b,j] = 0.001 * sum_{it<nit-1} noise[it,b,j];
//       out_u[b,0:16] = (u9 + 0.001*noise[nit-1])[b, 0:16]
// ---------------------------------------------------------------------------
__global__ void prep_kernel(const float* __restrict__ noise,
                            const int* __restrict__ nit_p,
                            float* __restrict__ out_u) {
    const int TOT = BB * HH * NUD;
    int idx = blockIdx.x * blockDim.x + threadIdx.x;
    if (idx >= TOT) return;
    int nit = *nit_p;
    float s = 0.f;
    for (int it = 0; it < nit - 1; ++it)
        s += noise[(size_t)it * TOT + idx];
    float u9 = 0.001f * s;
    g_u9[idx] = u9;
    int rem = idx % (HH * NUD);
    if (rem < NUD) {
        float u10 = u9 + 0.001f * noise[(size_t)(nit - 1) * TOT + idx];
        int b = idx / (HH * NUD);
        out_u[b * NUD + rem] = u10;
    }
}

__device__ __forceinline__ float dot4(float4 a, float4 b) {
    return a.x * b.x + a.y * b.y + a.z * b.z + a.w * b.w;
}

// ---------------------------------------------------------------------------
// Main: fused rollout + linearization.
// grid = 128 CTAs x 256 threads. Each warp carries R=4 batch rows.
// ---------------------------------------------------------------------------
__global__ __launch_bounds__(256, 1)
void mpc_kernel(const float* __restrict__ x0,
                const float* __restrict__ W1g,   // [80,256]
                const float* __restrict__ b1g,   // [256]
                const float* __restrict__ W2g,   // [256,64]
                float* __restrict__ out_xtraj,   // [B,51,64]
                float* __restrict__ out_xpred,   // [B,50,64]
                float* __restrict__ out_gx,      // [B,50,64]
                float* __restrict__ out_gu) {    // [B,50,16]
    extern __shared__ float smem[];
    float* W1s  = smem;                      // [80][260]
    float* W2Ts = W1s + ZD * W1STRIDE;       // [64][260]  W2Ts[i][m] = W2[m][i]
    float* c2s  = W2Ts + NXD * W2STRIDE;     // [256]
    float* b1s  = c2s + HIDD;                // [256]
    float* zall = b1s + HIDD;                // [8 warps][4 rows][80]
    float* tall = zall + 8 * 4 * ZD;         // [8 warps][4 rows][256]

    const int tid = threadIdx.x;

    // Stage W1 (padded) and W2^T (padded)
    for (int idx = tid; idx < ZD * HIDD; idx += 256) {
        int i = idx >> 8, m = idx & 255;
        W1s[i * W1STRIDE + m] = W1g[idx];
    }
    for (int idx = tid; idx < HIDD * NXD; idx += 256) {
        int m = idx >> 6, j = idx & 63;
        W2Ts[j * W2STRIDE + m] = W2g[idx];
    }
    {   // c2[m] = 0.1 * rowsum(W2[m,:]);  b1 staged
        int m = tid;  // 256 threads, 256 values
        float s = 0.f;
        #pragma unroll 8
        for (int j = 0; j < NXD; ++j) s += W2g[m * NXD + j];
        c2s[m] = 0.1f * s;
        b1s[m] = b1g[m];
    }
    __syncthreads();

    const int w = tid >> 5, lane = tid & 31;
    float* z_sm = zall + w * 4 * ZD;     // per-warp [4][80] : z = [x | u]
    float* t_sm = tall + w * 4 * HIDD;   // per-warp [4][256]: t, then gh
    const int b0 = blockIdx.x * 32 + w * 4;

    float c2r[8], b1r[8];
    #pragma unroll
    for (int j = 0; j < 8; ++j) {
        c2r[j] = c2s[j * 32 + lane];
        b1r[j] = b1s[j * 32 + lane];
    }

    // Init state + write x_traj[:,0,:]
    #pragma unroll
    for (int r = 0; r < 4; ++r) {
        int b = b0 + r;
        float xa = x0[b * NXD + lane];
        float xb = x0[b * NXD + 32 + lane];
        z_sm[r * ZD + lane] = xa;
        z_sm[r * ZD + 32 + lane] = xb;
        size_t base = (size_t)b * (HH + 1) * NXD;
        out_xtraj[base + lane] = xa;
        out_xtraj[base + 32 + lane] = xb;
    }

    const float4* wrow_a = (const float4*)&W2Ts[lane * W2STRIDE];
    const float4* wrow_b = (const float4*)&W2Ts[(lane + 32) * W2STRIDE];
    const float4* w1a = (const float4*)&W1s[lane * W1STRIDE];
    const float4* w1b = (const float4*)&W1s[(lane + 32) * W1STRIDE];
    const float4* w1c = (const float4*)&W1s[(NXD + (lane & 15)) * W1STRIDE];

    for (int k = 0; k < HH; ++k) {
        // Stage this step's controls into z[:, 64:80] (2 rows per 32 lanes)
        #pragma unroll
        for (int p = 0; p < 2; ++p) {
            int r = p * 2 + (lane >> 4);
            int i = lane & 15;
            z_sm[r * ZD + NXD + i] =
                g_u9[(size_t)(b0 + r) * HH * NUD + k * NUD + i];
        }
        __syncwarp();

        // ---- GEMV1: h = z @ W1 + b1   (m = j*32+lane per lane, 4 rows) ----
        float h0[8], h1[8], h2[8], h3[8];
        #pragma unroll
        for (int j = 0; j < 8; ++j) { h0[j] = b1r[j]; h1[j] = b1r[j]; h2[j] = b1r[j]; h3[j] = b1r[j]; }
        #pragma unroll 4
        for (int i = 0; i < ZD; ++i) {
            float w8[8];
            #pragma unroll
            for (int j = 0; j < 8; ++j) w8[j] = W1s[i * W1STRIDE + j * 32 + lane];
            float z0 = z_sm[0 * ZD + i];
            float z1 = z_sm[1 * ZD + i];
            float z2 = z_sm[2 * ZD + i];
            float z3 = z_sm[3 * ZD + i];
            #pragma unroll
            for (int j = 0; j < 8; ++j) {
                h0[j] += z0 * w8[j];
                h1[j] += z1 * w8[j];
                h2[j] += z2 * w8[j];
                h3[j] += z3 * w8[j];
            }
        }

        // ---- tanh, stage t for broadcast ----
        float t0[8], t1[8], t2[8], t3[8];
        #pragma unroll
        for (int j = 0; j < 8; ++j) {
            t0[j] = tanhf(h0[j]); t1[j] = tanhf(h1[j]);
            t2[j] = tanhf(h2[j]); t3[j] = tanhf(h3[j]);
            int mi = j * 32 + lane;
            t_sm[0 * HIDD + mi] = t0[j];
            t_sm[1 * HIDD + mi] = t1[j];
            t_sm[2 * HIDD + mi] = t2[j];
            t_sm[3 * HIDD + mi] = t3[j];
        }
        __syncwarp();

        // ---- GEMV2: x_next = x + 0.1 * t @ W2  (lane owns cols lane, lane+32) ----
        float acc[4][2];
        #pragma unroll
        for (int r = 0; r < 4; ++r) { acc[r][0] = 0.f; acc[r][1] = 0.f; }
        #pragma unroll 4
        for (int q = 0; q < HIDD / 4; ++q) {
            float4 wa = wrow_a[q];
            float4 wb = wrow_b[q];
            #pragma unroll
            for (int r = 0; r < 4; ++r) {
                float4 tv = *(const float4*)&t_sm[r * HIDD + 4 * q];
                acc[r][0] += dot4(tv, wa);
                acc[r][1] += dot4(tv, wb);
            }
        }
        #pragma unroll
        for (int r = 0; r < 4; ++r) {
            int b = b0 + r;
            float xn0 = z_sm[r * ZD + lane]      + 0.1f * acc[r][0];
            float xn1 = z_sm[r * ZD + 32 + lane] + 0.1f * acc[r][1];
            size_t base_t = (size_t)b * (HH + 1) * NXD + (size_t)(k + 1) * NXD;
            size_t base_p = (size_t)b * HH * NXD + (size_t)k * NXD;
            out_xtraj[base_t + lane] = xn0;
            out_xtraj[base_t + 32 + lane] = xn1;
            out_xpred[base_p + lane] = xn0;
            out_xpred[base_p + 32 + lane] = xn1;
            z_sm[r * ZD + lane] = xn0;
            z_sm[r * ZD + 32 + lane] = xn1;
        }

        // ---- gh = c2 * (1 - t^2), staged into t_sm ----
        __syncwarp();  // all lanes done reading t before overwrite
        #pragma unroll
        for (int j = 0; j < 8; ++j) {
            int mi = j * 32 + lane;
            t_sm[0 * HIDD + mi] = c2r[j] * (1.f - t0[j] * t0[j]);
            t_sm[1 * HIDD + mi] = c2r[j] * (1.f - t1[j] * t1[j]);
            t_sm[2 * HIDD + mi] = c2r[j] * (1.f - t2[j] * t2[j]);
            t_sm[3 * HIDD + mi] = c2r[j] * (1.f - t3[j] * t3[j]);
        }
        __syncwarp();

        // ---- grad GEMV: g[i] = sum_m gh[m]*W1[i,m]  (lane owns i=lane, lane+32, 64+(lane&15)) ----
        float ga[4] = {0.f, 0.f, 0.f, 0.f};
        float gb[4] = {0.f, 0.f, 0.f, 0.f};
        float gc[4] = {0.f, 0.f, 0.f, 0.f};
        #pragma unroll 4
        for (int q = 0; q < HIDD / 4; ++q) {
            float4 wa = w1a[q];
            float4 wb = w1b[q];
            float4 wc = w1c[q];
            #pragma unroll
            for (int r = 0; r < 4; ++r) {
                float4 g = *(const float4*)&t_sm[r * HIDD + 4 * q];
                ga[r] += dot4(g, wa);
                gb[r] += dot4(g, wb);
                gc[r] += dot4(g, wc);
            }
        }
        #pragma unroll
        for (int r = 0; r < 4; ++r) {
            int b = b0 + r;
            size_t base_gx = (size_t)b * HH * NXD + (size_t)k * NXD;
            out_gx[base_gx + lane] = 1.f + ga[r];
            out_gx[base_gx + 32 + lane] = 1.f + gb[r];
            if (lane < NUD)
                out_gu[(size_t)b * HH * NUD + (size_t)k * NUD + lane] = gc[r];
        }
        // next-iter top __syncwarp() orders t_sm/z_sm reuse
    }
}

// ---------------------------------------------------------------------------
extern "C" void kernel_launch(void* const* d_in, const int* in_sizes, int n_in,
                              void* d_out, int out_size) {
    const float* x0    = (const float*)d_in[0];
    // d_in[1] = xref (unused: zeros, never reaches outputs)
    const float* W1    = (const float*)d_in[2];
    const float* b1    = (const float*)d_in[3];
    const float* W2    = (const float*)d_in[4];
    const float* noise = (const float*)d_in[5];
    const int*   nit   = (const int*)d_in[6];

    float* out = (float*)d_out;
    float* out_u     = out + OFF_U;
    float* out_xtraj = out + OFF_XTRAJ;
    float* out_xpred = out + OFF_XPRED;
    float* out_gx    = out + OFF_GX;
    float* out_gu    = out + OFF_GU;

    // Prep: u9 scratch + u output
    {
        int tot = BB * HH * NUD;
        prep_kernel<<<(tot + 255) / 256, 256>>>(noise, nit, out_u);
    }

    // Main fused rollout + linearization
    const size_t smem_bytes =
        (ZD * W1STRIDE + NXD * W2STRIDE + HIDD + HIDD + 8 * 4 * ZD + 8 * 4 * HIDD)
        * sizeof(float);  // 194,816 B
    cudaFuncSetAttribute(mpc_kernel,
                         cudaFuncAttributeMaxDynamicSharedMemorySize,
                         (int)smem_bytes);
    mpc_kernel<<<BB / 32, 256, smem_bytes>>>(x0, W1, b1, W2,
                                             out_xtraj, out_xpred,
                                             out_gx, out_gu);
}

// round 5
// speedup vs baseline: 1.1172x; 1.1172x over previous
#include <cuda_runtime.h>
#include <cstddef>

// Problem constants
#define BB    4096
#define NXD   64
#define NUD   16
#define HH    50
#define HIDD  256
#define ZD    80
#define W1STRIDE 260    // floats; %4==0 (16B align), 4-bank skew per row -> conflict-free LDS.128
#define W2STRIDE 260

// Output layout
#define OFF_U      0
#define OFF_XTRAJ  (BB*NUD)
#define OFF_XPRED  (OFF_XTRAJ + BB*(HH+1)*NXD)
#define OFF_GX     (OFF_XPRED + BB*HH*NXD)
#define OFF_GU     (OFF_GX + BB*HH*NXD)

typedef unsigned long long ull;

__device__ float g_u9[BB * HH * NUD];

union F2U { ull u; float2 f; };

__device__ __forceinline__ ull fma2(ull a, ull b, ull c) {
    ull d;
    asm("fma.rn.f32x2 %0, %1, %2, %3;" : "=l"(d) : "l"(a), "l"(b), "l"(c));
    return d;
}
__device__ __forceinline__ ull mul2(ull a, ull b) {
    ull d;
    asm("mul.rn.f32x2 %0, %1, %2;" : "=l"(d) : "l"(a), "l"(b));
    return d;
}
// tanh(x) = 1 - 2/(exp2(2*log2e*x)+1): 2 MUFU + 3 fma-class ops, err ~1e-6
__device__ __forceinline__ float tanhfast(float x) {
    float e, r;
    asm("ex2.approx.f32 %0, %1;" : "=f"(e) : "f"(x * 2.885390081777927f));
    asm("rcp.approx.f32 %0, %1;" : "=f"(r) : "f"(e + 1.0f));
    return fmaf(-2.0f, r, 1.0f);
}

// ---------------------------------------------------------------------------
__global__ void prep_kernel(const float* __restrict__ noise,
                            const int* __restrict__ nit_p,
                            float* __restrict__ out_u) {
    const int TOT = BB * HH * NUD;
    int idx = blockIdx.x * blockDim.x + threadIdx.x;
    if (idx >= TOT) return;
    int nit = *nit_p;
    float s = 0.f;
    for (int it = 0; it < nit - 1; ++it)
        s += noise[(size_t)it * TOT + idx];
    float u9 = 0.001f * s;
    g_u9[idx] = u9;
    int rem = idx % (HH * NUD);
    if (rem < NUD) {
        float u10 = u9 + 0.001f * noise[(size_t)(nit - 1) * TOT + idx];
        int b = idx / (HH * NUD);
        out_u[b * NUD + rem] = u10;
    }
}

// ---------------------------------------------------------------------------
// grid = 128 CTAs x 256 threads; each warp carries 4 batch rows through 50 steps.
// All inner products use packed fma.rn.f32x2 with naturally-contiguous float2
// operands (no per-use packing).
// ---------------------------------------------------------------------------
__global__ __launch_bounds__(256, 1)
void mpc_kernel(const float* __restrict__ x0,
                const float* __restrict__ W1g,   // [80,256]
                const float* __restrict__ b1g,   // [256]
                const float* __restrict__ W2g,   // [256,64]
                float* __restrict__ out_xtraj,
                float* __restrict__ out_xpred,
                float* __restrict__ out_gx,
                float* __restrict__ out_gu) {
    extern __shared__ float smem[];
    float*  W1s  = smem;                           // [80][260]
    float*  W2Ts = W1s + ZD * W1STRIDE;            // [64][260] : W2Ts[c][m] = W2[m][c]
    float*  c2s  = W2Ts + NXD * W2STRIDE;          // [256]
    float*  b1s  = c2s + HIDD;                     // [256]
    float2* zdup = (float2*)(b1s + HIDD);          // [8 warps][4 rows][80] duplicated z
    float*  tall = (float*)(zdup + 8 * 4 * ZD);    // [8 warps][4 rows][256] t then gh

    const int tid = threadIdx.x;

    // ---- Stage weights ----
    for (int idx = tid; idx < ZD * HIDD; idx += 256) {
        int i = idx >> 8, m = idx & 255;
        W1s[i * W1STRIDE + m] = W1g[idx];
    }
    for (int idx = tid; idx < HIDD * NXD; idx += 256) {
        int m = idx >> 6, j = idx & 63;
        W2Ts[j * W2STRIDE + m] = W2g[idx];
    }
    {
        int m = tid;
        float s = 0.f;
        #pragma unroll 8
        for (int j = 0; j < NXD; ++j) s += W2g[m * NXD + j];
        c2s[m] = 0.1f * s;
        b1s[m] = b1g[m];
    }
    __syncthreads();

    const int w = tid >> 5, lane = tid & 31;
    float2* zd = zdup + w * 4 * ZD;      // per-warp [4][80]
    float*  tw = tall + w * 4 * HIDD;    // per-warp [4][256]
    const int b0 = blockIdx.x * 32 + w * 4;
    const int m2 = 2 * lane;             // lane owns m-pairs {m2+64j : j=0..3}

    // per-lane constant pairs
    ull b1p[4], c2p[4], nc2p[4];
    #pragma unroll
    for (int j = 0; j < 4; ++j) {
        b1p[j] = *(const ull*)&b1s[64 * j + m2];
        F2U c; c.u = *(const ull*)&c2s[64 * j + m2];
        c2p[j] = c.u;
        F2U n; n.f.x = -c.f.x; n.f.y = -c.f.y;
        nc2p[j] = n.u;
    }

    // ---- Init state: zdup + x_traj[:,0,:] ----
    #pragma unroll
    for (int r = 0; r < 4; ++r) {
        int b = b0 + r;
        float xa = x0[b * NXD + lane];
        float xb = x0[b * NXD + 32 + lane];
        zd[r * ZD + lane]      = make_float2(xa, xa);
        zd[r * ZD + 32 + lane] = make_float2(xb, xb);
        size_t base = (size_t)b * (HH + 1) * NXD;
        out_xtraj[base + lane]      = xa;
        out_xtraj[base + 32 + lane] = xb;
    }

    // u prefetch: per lane 2 of the 64 per-step controls
    const int ur0 = lane >> 4, ui = lane & 15;
    float up0 = g_u9[(size_t)(b0 + ur0) * HH * NUD + ui];
    float up1 = g_u9[(size_t)(b0 + 2 + ur0) * HH * NUD + ui];

    const ulonglong2* w2a = (const ulonglong2*)&W2Ts[lane * W2STRIDE];
    const ulonglong2* w2b = (const ulonglong2*)&W2Ts[(lane + 32) * W2STRIDE];
    const ulonglong2* wia = (const ulonglong2*)&W1s[lane * W1STRIDE];
    const ulonglong2* wib = (const ulonglong2*)&W1s[(32 + lane) * W1STRIDE];
    const ulonglong2* wic = (const ulonglong2*)&W1s[(64 + (lane & 15)) * W1STRIDE];

    for (int k = 0; k < HH; ++k) {
        // ---- stage controls (duplicated) ----
        zd[ur0 * ZD + NXD + ui]       = make_float2(up0, up0);
        zd[(2 + ur0) * ZD + NXD + ui] = make_float2(up1, up1);
        __syncwarp();
        if (k + 1 < HH) {
            up0 = g_u9[(size_t)(b0 + ur0) * HH * NUD + (k + 1) * NUD + ui];
            up1 = g_u9[(size_t)(b0 + 2 + ur0) * HH * NUD + (k + 1) * NUD + ui];
        }

        // ---- GEMV1: h = z @ W1 + b1  (m-pairs, z duplicated) ----
        ull h[4][4];
        #pragma unroll
        for (int r = 0; r < 4; ++r)
            #pragma unroll
            for (int j = 0; j < 4; ++j) h[r][j] = b1p[j];

        #pragma unroll 4
        for (int i = 0; i < ZD; ++i) {
            const float* wrow = &W1s[i * W1STRIDE];
            ull w0 = *(const ull*)&wrow[m2];
            ull w1 = *(const ull*)&wrow[m2 + 64];
            ull w2 = *(const ull*)&wrow[m2 + 128];
            ull w3 = *(const ull*)&wrow[m2 + 192];
            #pragma unroll
            for (int r = 0; r < 4; ++r) {
                ull z = *(const ull*)&zd[r * ZD + i];
                h[r][0] = fma2(z, w0, h[r][0]);
                h[r][1] = fma2(z, w1, h[r][1]);
                h[r][2] = fma2(z, w2, h[r][2]);
                h[r][3] = fma2(z, w3, h[r][3]);
            }
        }

        // ---- tanh + stage t ----
        ull t[4][4];
        #pragma unroll
        for (int r = 0; r < 4; ++r)
            #pragma unroll
            for (int j = 0; j < 4; ++j) {
                F2U hv; hv.u = h[r][j];
                F2U tv;
                tv.f.x = tanhfast(hv.f.x);
                tv.f.y = tanhfast(hv.f.y);
                t[r][j] = tv.u;
                *(ull*)&tw[r * HIDD + 64 * j + m2] = tv.u;
            }
        __syncwarp();

        // ---- GEMV2: x_next = x + 0.1 * t @ W2  (horizontal m-pairs) ----
        ull acc[4][2];
        #pragma unroll
        for (int r = 0; r < 4; ++r) { acc[r][0] = 0ull; acc[r][1] = 0ull; }
        #pragma unroll 4
        for (int q = 0; q < HIDD / 4; ++q) {
            ulonglong2 wa = w2a[q];
            ulonglong2 wb = w2b[q];
            #pragma unroll
            for (int r = 0; r < 4; ++r) {
                ulonglong2 tv = *(const ulonglong2*)&tw[r * HIDD + 4 * q];
                acc[r][0] = fma2(tv.x, wa.x, acc[r][0]);
                acc[r][0] = fma2(tv.y, wa.y, acc[r][0]);
                acc[r][1] = fma2(tv.x, wb.x, acc[r][1]);
                acc[r][1] = fma2(tv.y, wb.y, acc[r][1]);
            }
        }
        #pragma unroll
        for (int r = 0; r < 4; ++r) {
            int b = b0 + r;
            F2U a0; a0.u = acc[r][0];
            F2U a1; a1.u = acc[r][1];
            float xn0 = zd[r * ZD + lane].x      + 0.1f * (a0.f.x + a0.f.y);
            float xn1 = zd[r * ZD + 32 + lane].x + 0.1f * (a1.f.x + a1.f.y);
            size_t base_t = (size_t)b * (HH + 1) * NXD + (size_t)(k + 1) * NXD;
            size_t base_p = (size_t)b * HH * NXD + (size_t)k * NXD;
            out_xtraj[base_t + lane]      = xn0;
            out_xtraj[base_t + 32 + lane] = xn1;
            out_xpred[base_p + lane]      = xn0;
            out_xpred[base_p + 32 + lane] = xn1;
            zd[r * ZD + lane]      = make_float2(xn0, xn0);
            zd[r * ZD + 32 + lane] = make_float2(xn1, xn1);
        }

        // ---- gh = c2 * (1 - t^2), staged over t ----
        __syncwarp();  // all lanes done reading t
        #pragma unroll
        for (int r = 0; r < 4; ++r)
            #pragma unroll
            for (int j = 0; j < 4; ++j) {
                ull tt = mul2(t[r][j], t[r][j]);
                ull gh = fma2(tt, nc2p[j], c2p[j]);
                *(ull*)&tw[r * HIDD + 64 * j + m2] = gh;
            }
        __syncwarp();

        // ---- grad: g[i] = sum_m gh[m]*W1[i,m]  (horizontal m-pairs) ----
        ull ga[4], gb[4], gc[4];
        #pragma unroll
        for (int r = 0; r < 4; ++r) { ga[r] = 0ull; gb[r] = 0ull; gc[r] = 0ull; }
        #pragma unroll 4
        for (int q = 0; q < HIDD / 4; ++q) {
            ulonglong2 wa = wia[q];
            ulonglong2 wb = wib[q];
            ulonglong2 wc = wic[q];
            #pragma unroll
            for (int r = 0; r < 4; ++r) {
                ulonglong2 g = *(const ulonglong2*)&tw[r * HIDD + 4 * q];
                ga[r] = fma2(g.x, wa.x, ga[r]);
                ga[r] = fma2(g.y, wa.y, ga[r]);
                gb[r] = fma2(g.x, wb.x, gb[r]);
                gb[r] = fma2(g.y, wb.y, gb[r]);
                gc[r] = fma2(g.x, wc.x, gc[r]);
                gc[r] = fma2(g.y, wc.y, gc[r]);
            }
        }
        #pragma unroll
        for (int r = 0; r < 4; ++r) {
            int b = b0 + r;
            F2U va; va.u = ga[r];
            F2U vb; vb.u = gb[r];
            size_t base_gx = (size_t)b * HH * NXD + (size_t)k * NXD;
            out_gx[base_gx + lane]      = 1.f + va.f.x + va.f.y;
            out_gx[base_gx + 32 + lane] = 1.f + vb.f.x + vb.f.y;
            if (lane < NUD) {
                F2U vc; vc.u = gc[r];
                out_gu[(size_t)b * HH * NUD + (size_t)k * NUD + lane] =
                    vc.f.x + vc.f.y;
            }
        }
        __syncwarp();  // protect tw/zd reuse next step
    }
}

// ---------------------------------------------------------------------------
extern "C" void kernel_launch(void* const* d_in, const int* in_sizes, int n_in,
                              void* d_out, int out_size) {
    const float* x0    = (const float*)d_in[0];
    const float* W1    = (const float*)d_in[2];
    const float* b1    = (const float*)d_in[3];
    const float* W2    = (const float*)d_in[4];
    const float* noise = (const float*)d_in[5];
    const int*   nit   = (const int*)d_in[6];

    float* out = (float*)d_out;
    float* out_u     = out + OFF_U;
    float* out_xtraj = out + OFF_XTRAJ;
    float* out_xpred = out + OFF_XPRED;
    float* out_gx    = out + OFF_GX;
    float* out_gu    = out + OFF_GU;

    {
        int tot = BB * HH * NUD;
        prep_kernel<<<(tot + 255) / 256, 256>>>(noise, nit, out_u);
    }

    const size_t smem_bytes =
        (size_t)(ZD * W1STRIDE + NXD * W2STRIDE + HIDD + HIDD) * sizeof(float)
        + (size_t)(8 * 4 * ZD) * sizeof(float2)
        + (size_t)(8 * 4 * HIDD) * sizeof(float);   // 205,056 B
    cudaFuncSetAttribute(mpc_kernel,
                         cudaFuncAttributeMaxDynamicSharedMemorySize,
                         (int)smem_bytes);
    mpc_kernel<<<BB / 32, 256, smem_bytes>>>(x0, W1, b1, W2,
                                             out_xtraj, out_xpred,
                                             out_gx, out_gu);
}